// round 4
// baseline (speedup 1.0000x reference)
#include <cuda_runtime.h>
#include <math.h>

// ---------------- problem constants ----------------
#define TT 128   // seq len
#define BB 256   // batch
#define HH 512   // hidden
#define GG 2048  // 4*H gates
#define VV 128   // vocab
#define LL 128   // latent

typedef unsigned long long u64t;

// f32x2 packed helpers (sm_100+ PTX; FFMA2 in SASS — 2x fp32 throughput)
__device__ __forceinline__ u64t pack2(float x, float y) {
    u64t r; asm("mov.b64 %0, {%1, %2};" : "=l"(r) : "f"(x), "f"(y)); return r;
}
__device__ __forceinline__ void fma2(u64t& d, u64t a, u64t b) {
    asm("fma.rn.f32x2 %0, %1, %2, %0;" : "+l"(d) : "l"(a), "l"(b));
}
__device__ __forceinline__ float2 unpack2(u64t v) {
    float2 r; asm("mov.b64 {%0, %1}, %2;" : "=f"(r.x), "=f"(r.y) : "l"(v)); return r;
}

// ---------------- device scratch ----------------
__device__ float g_seq [TT*BB*HH];
__device__ float g_seq1[TT*BB*2*HH];
__device__ float g_preF[TT*BB*GG];
__device__ float g_preB[TT*BB*GG];
__device__ float g_y0f [TT*BB*HH];
__device__ float g_y0b [TT*BB*HH];
__device__ float g_y1f [TT*BB*HH];
__device__ float g_y1b [TT*BB*HH];
__device__ float g_c0f [BB*HH];
__device__ float g_c0b [BB*HH];
__device__ float g_c1f [BB*HH];
__device__ float g_c1b [BB*HH];
__device__ float g_zeros[BB*HH];     // never written -> stays zero
__device__ float g_z   [BB*LL];
__device__ float g_dh0 [BB*HH];
__device__ float g_dh1 [BB*HH];
__device__ float g_dc0 [BB*HH];
__device__ float g_dc1 [BB*HH];
__device__ float g_part0[BB*GG];
__device__ float g_part1[BB*GG];
__device__ int   g_tok [BB];

__device__ __forceinline__ float sigf(float v) { return 1.0f / (1.0f + expf(-v)); }

// ---------------- embedding gather ----------------
__global__ void embed_kernel(const int* __restrict__ x, const float* __restrict__ emb,
                             float* __restrict__ seq) {
    int total = TT*BB*HH;
    for (int i = blockIdx.x*blockDim.x + threadIdx.x; i < total; i += gridDim.x*blockDim.x) {
        int t = i / (BB*HH);
        int r = i % (BB*HH);
        int b = r / HH;
        int h = r % HH;
        seq[i] = emb[x[b*TT + t]*HH + h];
    }
}

// ---------------- concat ----------------
__global__ void concat_kernel(const float* __restrict__ yf, const float* __restrict__ yb,
                              float* __restrict__ seq1) {
    int total = TT*BB*2*HH;
    for (int i = blockIdx.x*blockDim.x + threadIdx.x; i < total; i += gridDim.x*blockDim.x) {
        int r = i / (2*HH);
        int j = i % (2*HH);
        seq1[i] = (j < HH) ? yf[r*HH + j] : yb[r*HH + j - HH];
    }
}

// ================= SGEMM (f32x2): C[M,N] = A[M,K] @ W[N,K]^T + bias[N] =================
#define PBM 128
#define PBN 128
#define PBK 16
#define PA_LD 132
#define PW_LD 132

__global__ __launch_bounds__(256) void sgemm_bias_f(const float* __restrict__ A,
                                                    const float* __restrict__ W,
                                                    const float* __restrict__ bias,
                                                    float* __restrict__ C,
                                                    int M, int N, int K) {
    __shared__ __align__(16) float As[PBK*PA_LD];
    __shared__ __align__(16) float Ws[PBK*PW_LD];
    const int bm = blockIdx.y * PBM;
    const int bn = blockIdx.x * PBN;
    const int tid = threadIdx.x;
    const int tx = tid % 16;
    const int ty = tid / 16;
    const int am = tid >> 1;
    const int ak = (tid & 1) * 8;

    const float* ap = A + (size_t)(bm + am)*K + ak;
    const float* wp = W + (size_t)(bn + am)*K + ak;

    float4 ra0 = *(const float4*)(ap);
    float4 ra1 = *(const float4*)(ap + 4);
    float4 rw0 = *(const float4*)(wp);
    float4 rw1 = *(const float4*)(wp + 4);

    u64t acc2[4][8];
    #pragma unroll
    for (int p = 0; p < 4; p++)
        #pragma unroll
        for (int j = 0; j < 8; j++) acc2[p][j] = 0ull;

    for (int k0 = 0; k0 < K; k0 += PBK) {
        As[(ak+0)*PA_LD + am] = ra0.x; As[(ak+1)*PA_LD + am] = ra0.y;
        As[(ak+2)*PA_LD + am] = ra0.z; As[(ak+3)*PA_LD + am] = ra0.w;
        As[(ak+4)*PA_LD + am] = ra1.x; As[(ak+5)*PA_LD + am] = ra1.y;
        As[(ak+6)*PA_LD + am] = ra1.z; As[(ak+7)*PA_LD + am] = ra1.w;
        Ws[(ak+0)*PW_LD + am] = rw0.x; Ws[(ak+1)*PW_LD + am] = rw0.y;
        Ws[(ak+2)*PW_LD + am] = rw0.z; Ws[(ak+3)*PW_LD + am] = rw0.w;
        Ws[(ak+4)*PW_LD + am] = rw1.x; Ws[(ak+5)*PW_LD + am] = rw1.y;
        Ws[(ak+6)*PW_LD + am] = rw1.z; Ws[(ak+7)*PW_LD + am] = rw1.w;
        __syncthreads();

        if (k0 + PBK < K) {
            ra0 = *(const float4*)(ap + k0 + PBK);
            ra1 = *(const float4*)(ap + k0 + PBK + 4);
            rw0 = *(const float4*)(wp + k0 + PBK);
            rw1 = *(const float4*)(wp + k0 + PBK + 4);
        }

        #pragma unroll
        for (int k = 0; k < PBK; k++) {
            ulonglong2 A0 = *(const ulonglong2*)&As[k*PA_LD + ty*8];
            ulonglong2 A1 = *(const ulonglong2*)&As[k*PA_LD + ty*8 + 4];
            u64t apair[4] = {A0.x, A0.y, A1.x, A1.y};
            float w[8];
            *(float4*)&w[0] = *(const float4*)&Ws[k*PW_LD + tx*8];
            *(float4*)&w[4] = *(const float4*)&Ws[k*PW_LD + tx*8 + 4];
            #pragma unroll
            for (int j = 0; j < 8; j++) {
                u64t w2 = pack2(w[j], w[j]);
                #pragma unroll
                for (int p = 0; p < 4; p++) fma2(acc2[p][j], apair[p], w2);
            }
        }
        __syncthreads();
    }

    float bb[8];
    *(float4*)&bb[0] = *(const float4*)(bias + bn + tx*8);
    *(float4*)&bb[4] = *(const float4*)(bias + bn + tx*8 + 4);
    #pragma unroll
    for (int p = 0; p < 4; p++) {
        float2 v[8];
        #pragma unroll
        for (int j = 0; j < 8; j++) v[j] = unpack2(acc2[p][j]);
        #pragma unroll
        for (int sub = 0; sub < 2; sub++) {
            size_t row = (size_t)(bm + ty*8 + 2*p + sub)*N + bn + tx*8;
            float o[8];
            #pragma unroll
            for (int j = 0; j < 8; j++) o[j] = (sub ? v[j].y : v[j].x) + bb[j];
            *(float4*)&C[row]     = *(float4*)&o[0];
            *(float4*)&C[row + 4] = *(float4*)&o[4];
        }
    }
}

// ============ 4-gate K=512 GEMM core (32 batch x 32 hcols x 4 gates, f32x2) ============
// 256 threads, 2 blocks/SM. tx = col (0..31), ty = row-quad (0..7).
// Per thread: 4 rows (2 pairs) x 1 col x 4 gates = 8 u64 accumulators.
// W staged in smem as duplicated (w,w) u64 -> inner loop has zero pack MOVs.
#define RBM 32
#define RBN 32
#define RBK 32
#define HS_LD 36
#define WS2_LD 33

template<bool GATHER>
__device__ __forceinline__ void gate_gemm512(const float* __restrict__ Abase,
                                             const int* __restrict__ tok,
                                             const float* __restrict__ emb,
                                             const float* __restrict__ W,
                                             int bm, int bn,
                                             float* __restrict__ Hs,
                                             u64t* __restrict__ Ws2,
                                             u64t acc2[4][2]) {
    const int tid = threadIdx.x;
    const int tx = tid & 31;
    const int ty = tid >> 5;
    const int hm = tid >> 3;         // 0..31
    const int hk = (tid & 7) * 4;    // 0,4,...,28
    const int wr = tid >> 1;         // 0..127
    const int wg = wr >> 5;          // gate 0..3
    const int wn = wr & 31;          // col 0..31
    const int wk = (tid & 1) * 16;   // 0 or 16

    const float* hp;
    if (GATHER) hp = emb + (size_t)tok[bm + hm]*HH + hk;
    else        hp = Abase + (size_t)(bm + hm)*HH + hk;
    const float* wp = W + (size_t)(wg*HH + bn + wn)*HH + wk;

    float4 ha = *(const float4*)(hp);
    float4 wa0 = *(const float4*)(wp);
    float4 wa1 = *(const float4*)(wp + 4);
    float4 wa2 = *(const float4*)(wp + 8);
    float4 wa3 = *(const float4*)(wp + 12);

    for (int kt = 0; kt < HH; kt += RBK) {
        Hs[(hk+0)*HS_LD + hm] = ha.x;
        Hs[(hk+1)*HS_LD + hm] = ha.y;
        Hs[(hk+2)*HS_LD + hm] = ha.z;
        Hs[(hk+3)*HS_LD + hm] = ha.w;
        {
            u64t* wb = Ws2 + (size_t)(wg*RBK + wk)*WS2_LD + wn;
            wb[ 0*WS2_LD] = pack2(wa0.x, wa0.x); wb[ 1*WS2_LD] = pack2(wa0.y, wa0.y);
            wb[ 2*WS2_LD] = pack2(wa0.z, wa0.z); wb[ 3*WS2_LD] = pack2(wa0.w, wa0.w);
            wb[ 4*WS2_LD] = pack2(wa1.x, wa1.x); wb[ 5*WS2_LD] = pack2(wa1.y, wa1.y);
            wb[ 6*WS2_LD] = pack2(wa1.z, wa1.z); wb[ 7*WS2_LD] = pack2(wa1.w, wa1.w);
            wb[ 8*WS2_LD] = pack2(wa2.x, wa2.x); wb[ 9*WS2_LD] = pack2(wa2.y, wa2.y);
            wb[10*WS2_LD] = pack2(wa2.z, wa2.z); wb[11*WS2_LD] = pack2(wa2.w, wa2.w);
            wb[12*WS2_LD] = pack2(wa3.x, wa3.x); wb[13*WS2_LD] = pack2(wa3.y, wa3.y);
            wb[14*WS2_LD] = pack2(wa3.z, wa3.z); wb[15*WS2_LD] = pack2(wa3.w, wa3.w);
        }
        __syncthreads();

        if (kt + RBK < HH) {
            ha  = *(const float4*)(hp + kt + RBK);
            wa0 = *(const float4*)(wp + kt + RBK);
            wa1 = *(const float4*)(wp + kt + RBK + 4);
            wa2 = *(const float4*)(wp + kt + RBK + 8);
            wa3 = *(const float4*)(wp + kt + RBK + 12);
        }

        #pragma unroll
        for (int k = 0; k < RBK; k++) {
            ulonglong2 ap = *(const ulonglong2*)&Hs[k*HS_LD + ty*4]; // rows ty*4..ty*4+3
            #pragma unroll
            for (int g = 0; g < 4; g++) {
                u64t w2 = Ws2[(g*RBK + k)*WS2_LD + tx];
                fma2(acc2[g][0], ap.x, w2);
                fma2(acc2[g][1], ap.y, w2);
            }
        }
        __syncthreads();
    }
}

// LSTM elementwise epilogue (4 rows x 1 col per thread)
__device__ __forceinline__ void lstm_epilogue(u64t acc2[4][2],
                                              const float* __restrict__ pre,
                                              const float* __restrict__ cin,
                                              float* __restrict__ cout,
                                              float* __restrict__ hout,
                                              int bm, int bn) {
    const int tx = threadIdx.x & 31;
    const int ty = threadIdx.x >> 5;
    const int n = bn + tx;
    #pragma unroll
    for (int pr = 0; pr < 2; pr++) {
        float2 vi = unpack2(acc2[0][pr]);
        float2 vf = unpack2(acc2[1][pr]);
        float2 vg = unpack2(acc2[2][pr]);
        float2 vo = unpack2(acc2[3][pr]);
        #pragma unroll
        for (int sub = 0; sub < 2; sub++) {
            int b = bm + ty*4 + pr*2 + sub;
            const float* pb = pre + (size_t)b*GG;
            float gi = pb[0*HH + n] + (sub ? vi.y : vi.x);
            float gf = pb[1*HH + n] + (sub ? vf.y : vf.x);
            float gg = pb[2*HH + n] + (sub ? vg.y : vg.x);
            float go = pb[3*HH + n] + (sub ? vo.y : vo.x);
            float cn = sigf(gf)*cin[(size_t)b*HH + n] + sigf(gi)*tanhf(gg);
            cout[(size_t)b*HH + n] = cn;
            hout[(size_t)b*HH + n] = sigf(go)*tanhf(cn);
        }
    }
}

// ---------------- encoder recurrent step (both dirs via grid.z) ----------------
struct DirArgs {
    const float* pre;
    const float* hin;
    const float* cin;
    float* cout;
    float* hout;
    const float* Whh;
};

__global__ __launch_bounds__(256, 2) void lstm_step2(DirArgs A0, DirArgs A1) {
    __shared__ __align__(16) float Hs[RBK*HS_LD];
    __shared__ __align__(16) u64t Ws2[4*RBK*WS2_LD];
    DirArgs d = blockIdx.z ? A1 : A0;
    int bm = blockIdx.y * RBM;
    int bn = blockIdx.x * RBN;
    u64t acc2[4][2];
    #pragma unroll
    for (int g = 0; g < 4; g++) { acc2[g][0] = 0ull; acc2[g][1] = 0ull; }
    gate_gemm512<false>(d.hin, nullptr, nullptr, d.Whh, bm, bn, Hs, Ws2, acc2);
    lstm_epilogue(acc2, d.pre, d.cin, d.cout, d.hout, bm, bn);
}

// ---------------- decoder fused step (cell via z=0, partial via z=1) ----------------
struct CellArgs {
    const float* A;
    const int*   tok;
    const float* W;
    const float* partial;
    float* c;
    float* h;
};
struct PartArgs {
    const float* A;
    const float* W;
    const float* bias;
    float* outp;
};

__global__ __launch_bounds__(256, 2) void dec_step(CellArgs ca, PartArgs pa,
                                                   const float* __restrict__ emb) {
    __shared__ __align__(16) float Hs[RBK*HS_LD];
    __shared__ __align__(16) u64t Ws2[4*RBK*WS2_LD];
    int bm = blockIdx.y * RBM;
    int bn = blockIdx.x * RBN;
    u64t acc2[4][2];
    #pragma unroll
    for (int g = 0; g < 4; g++) { acc2[g][0] = 0ull; acc2[g][1] = 0ull; }

    if (blockIdx.z == 0) {
        if (ca.tok) gate_gemm512<true >(nullptr, ca.tok, emb, ca.W, bm, bn, Hs, Ws2, acc2);
        else        gate_gemm512<false>(ca.A,   nullptr, nullptr, ca.W, bm, bn, Hs, Ws2, acc2);
        lstm_epilogue(acc2, ca.partial, ca.c, ca.c, ca.h, bm, bn);
    } else {
        gate_gemm512<false>(pa.A, nullptr, nullptr, pa.W, bm, bn, Hs, Ws2, acc2);
        const int tx = threadIdx.x & 31;
        const int ty = threadIdx.x >> 5;
        const int n = bn + tx;
        #pragma unroll
        for (int g = 0; g < 4; g++) {
            float bv = pa.bias[g*HH + n];
            #pragma unroll
            for (int pr = 0; pr < 2; pr++) {
                float2 v = unpack2(acc2[g][pr]);
                int b0 = bm + ty*4 + pr*2;
                pa.outp[(size_t)(b0+0)*GG + g*HH + n] = v.x + bv;
                pa.outp[(size_t)(b0+1)*GG + g*HH + n] = v.y + bv;
            }
        }
    }
}

// ---------------- mu/logvar heads ----------------
__global__ __launch_bounds__(256) void head_kernel(const float* __restrict__ hf,
                                                   const float* __restrict__ hb,
                                                   const float* __restrict__ Wmu,
                                                   const float* __restrict__ bmu,
                                                   const float* __restrict__ Wlv,
                                                   const float* __restrict__ blv,
                                                   float* __restrict__ out_mu,
                                                   float* __restrict__ out_lv,
                                                   float* __restrict__ zbuf) {
    int b = blockIdx.x;
    int tid = threadIdx.x;
    __shared__ float sh[2*HH];
    for (int i = tid; i < HH; i += 256) {
        sh[i]      = hf[b*HH + i];
        sh[HH + i] = hb[b*HH + i];
    }
    __syncthreads();
    const float* W;
    float acc;
    int l;
    if (tid < LL) { l = tid;      W = Wmu + (size_t)l*2*HH; acc = bmu[l]; }
    else          { l = tid - LL; W = Wlv + (size_t)l*2*HH; acc = blv[l]; }
    #pragma unroll 8
    for (int k = 0; k < 2*HH; k++) acc += sh[k]*W[k];
    if (tid < LL) { out_mu[b*LL + l] = acc; zbuf[b*LL + l] = acc; }
    else          { out_lv[b*LL + l] = acc; }
}

// ---------------- decoder init ----------------
__global__ __launch_bounds__(512) void dec_init_kernel(const float* __restrict__ z,
                                                       const float* __restrict__ W,
                                                       const float* __restrict__ bias,
                                                       float* __restrict__ h0,
                                                       float* __restrict__ h1,
                                                       float* __restrict__ c0,
                                                       float* __restrict__ c1,
                                                       int* __restrict__ tok) {
    int b = blockIdx.x;
    int tid = threadIdx.x;
    __shared__ float sz[LL];
    if (tid < LL) sz[tid] = z[b*LL + tid];
    __syncthreads();
    float acc = bias[tid];
    const float* w = W + (size_t)tid*LL;
    #pragma unroll 8
    for (int k = 0; k < LL; k++) acc += sz[k]*w[k];
    h0[b*HH + tid] = acc;
    h1[b*HH + tid] = acc;
    c0[b*HH + tid] = 0.0f;
    c1[b*HH + tid] = 0.0f;
    if (tid == 0) tok[b] = 1;
}

// ---------------- logits + argmax ----------------
__global__ __launch_bounds__(128) void logits_argmax_kernel(const float* __restrict__ h1,
                                                            const float* __restrict__ W,
                                                            const float* __restrict__ bias,
                                                            float* __restrict__ recon,
                                                            int t,
                                                            int* __restrict__ tok) {
    int v = threadIdx.x;
    int b0 = blockIdx.x * 4;
    __shared__ float sh[4][HH];
    for (int i = v; i < 4*HH/4; i += 128) {
        ((float4*)&sh[0][0])[i] = ((const float4*)(h1 + (size_t)b0*HH))[i];
    }
    __syncthreads();
    float bv = bias[v];
    float acc0 = bv, acc1 = bv, acc2 = bv, acc3 = bv;
    const float4* w4 = (const float4*)(W + (size_t)v*HH);
    #pragma unroll 4
    for (int k = 0; k < HH/4; k++) {
        float4 wv = w4[k];
        float4 s0 = *(const float4*)&sh[0][k*4];
        float4 s1 = *(const float4*)&sh[1][k*4];
        float4 s2 = *(const float4*)&sh[2][k*4];
        float4 s3 = *(const float4*)&sh[3][k*4];
        acc0 += s0.x*wv.x + s0.y*wv.y + s0.z*wv.z + s0.w*wv.w;
        acc1 += s1.x*wv.x + s1.y*wv.y + s1.z*wv.z + s1.w*wv.w;
        acc2 += s2.x*wv.x + s2.y*wv.y + s2.z*wv.z + s2.w*wv.w;
        acc3 += s3.x*wv.x + s3.y*wv.y + s3.z*wv.z + s3.w*wv.w;
    }
    __shared__ float sv[4][128];
    __shared__ int   si[4][128];
    float accs[4] = {acc0, acc1, acc2, acc3};
    #pragma unroll
    for (int i = 0; i < 4; i++) {
        recon[(size_t)(b0+i)*TT*VV + (size_t)t*VV + v] = accs[i];
        sv[i][v] = accs[i];
        si[i][v] = v;
    }
    __syncthreads();
    for (int s = 64; s > 0; s >>= 1) {
        if (v < s) {
            #pragma unroll
            for (int i = 0; i < 4; i++) {
                float ov = sv[i][v+s]; int oi = si[i][v+s];
                if (ov > sv[i][v] || (ov == sv[i][v] && oi < si[i][v])) {
                    sv[i][v] = ov; si[i][v] = oi;
                }
            }
        }
        __syncthreads();
    }
    if (v < 4) tok[b0 + v] = si[v][0];
}

// =================================== host launcher ====================================
extern "C" void kernel_launch(void* const* d_in, const int* in_sizes, int n_in,
                              void* d_out, int out_size) {
    const int*   x           = (const int*)  d_in[0];
    const float* emb         = (const float*)d_in[1];
    const float* enc_wih_l0  = (const float*)d_in[2];
    const float* enc_whh_l0  = (const float*)d_in[3];
    const float* enc_b_l0    = (const float*)d_in[4];
    const float* enc_wih_l1  = (const float*)d_in[5];
    const float* enc_whh_l1  = (const float*)d_in[6];
    const float* enc_b_l1    = (const float*)d_in[7];
    const float* fc_mu_w     = (const float*)d_in[8];
    const float* fc_mu_b     = (const float*)d_in[9];
    const float* fc_lv_w     = (const float*)d_in[10];
    const float* fc_lv_b     = (const float*)d_in[11];
    const float* dec_in_w    = (const float*)d_in[12];
    const float* dec_in_b    = (const float*)d_in[13];
    const float* dec_wih     = (const float*)d_in[14];
    const float* dec_whh     = (const float*)d_in[15];
    const float* dec_b       = (const float*)d_in[16];
    const float* dec_out_w   = (const float*)d_in[17];
    const float* dec_out_b   = (const float*)d_in[18];

    float* out       = (float*)d_out;
    float* out_recon = out;
    float* out_mu    = out + (size_t)BB*TT*VV;
    float* out_lv    = out_mu + (size_t)BB*LL;

    float *seq, *seq1, *preF, *preB, *y0f, *y0b, *y1f, *y1b;
    float *c0f, *c0b, *c1f, *c1b, *zeros, *zbuf, *dh0, *dh1, *dc0, *dc1;
    float *part0, *part1;
    int* tokp;
    cudaGetSymbolAddress((void**)&seq,   g_seq);
    cudaGetSymbolAddress((void**)&seq1,  g_seq1);
    cudaGetSymbolAddress((void**)&preF,  g_preF);
    cudaGetSymbolAddress((void**)&preB,  g_preB);
    cudaGetSymbolAddress((void**)&y0f,   g_y0f);
    cudaGetSymbolAddress((void**)&y0b,   g_y0b);
    cudaGetSymbolAddress((void**)&y1f,   g_y1f);
    cudaGetSymbolAddress((void**)&y1b,   g_y1b);
    cudaGetSymbolAddress((void**)&c0f,   g_c0f);
    cudaGetSymbolAddress((void**)&c0b,   g_c0b);
    cudaGetSymbolAddress((void**)&c1f,   g_c1f);
    cudaGetSymbolAddress((void**)&c1b,   g_c1b);
    cudaGetSymbolAddress((void**)&zeros, g_zeros);
    cudaGetSymbolAddress((void**)&zbuf,  g_z);
    cudaGetSymbolAddress((void**)&dh0,   g_dh0);
    cudaGetSymbolAddress((void**)&dh1,   g_dh1);
    cudaGetSymbolAddress((void**)&dc0,   g_dc0);
    cudaGetSymbolAddress((void**)&dc1,   g_dc1);
    cudaGetSymbolAddress((void**)&part0, g_part0);
    cudaGetSymbolAddress((void**)&part1, g_part1);
    cudaGetSymbolAddress((void**)&tokp,  g_tok);

    // 1) embedding
    embed_kernel<<<2048, 256>>>(x, emb, seq);

    // 2) encoder layer 0 pre-GEMMs
    dim3 preGrd(GG/PBN, (TT*BB)/PBM);
    sgemm_bias_f<<<preGrd, 256>>>(seq, enc_wih_l0,                 enc_b_l0,      preF, TT*BB, GG, HH);
    sgemm_bias_f<<<preGrd, 256>>>(seq, enc_wih_l0 + (size_t)GG*HH, enc_b_l0 + GG, preB, TT*BB, GG, HH);

    dim3 stepGrd(HH/RBN, BB/RBM, 2);   // (16, 8, 2) = 256 blocks
    for (int s = 0; s < TT; s++) {
        int tf = s, tb = TT-1-s;
        DirArgs df = { preF + (size_t)tf*BB*GG,
                       (s ? y0f + (size_t)(tf-1)*BB*HH : zeros),
                       (s ? c0f : zeros), c0f,
                       y0f + (size_t)tf*BB*HH,
                       enc_whh_l0 };
        DirArgs db = { preB + (size_t)tb*BB*GG,
                       (s ? y0b + (size_t)(tb+1)*BB*HH : zeros),
                       (s ? c0b : zeros), c0b,
                       y0b + (size_t)tb*BB*HH,
                       enc_whh_l0 + (size_t)GG*HH };
        lstm_step2<<<stepGrd, 256>>>(df, db);
    }

    // 3) encoder layer 1
    concat_kernel<<<2048, 256>>>(y0f, y0b, seq1);
    sgemm_bias_f<<<preGrd, 256>>>(seq1, enc_wih_l1,                   enc_b_l1,      preF, TT*BB, GG, 2*HH);
    sgemm_bias_f<<<preGrd, 256>>>(seq1, enc_wih_l1 + (size_t)GG*2*HH, enc_b_l1 + GG, preB, TT*BB, GG, 2*HH);
    for (int s = 0; s < TT; s++) {
        int tf = s, tb = TT-1-s;
        DirArgs df = { preF + (size_t)tf*BB*GG,
                       (s ? y1f + (size_t)(tf-1)*BB*HH : zeros),
                       (s ? c1f : zeros), c1f,
                       y1f + (size_t)tf*BB*HH,
                       enc_whh_l1 };
        DirArgs db = { preB + (size_t)tb*BB*GG,
                       (s ? y1b + (size_t)(tb+1)*BB*HH : zeros),
                       (s ? c1b : zeros), c1b,
                       y1b + (size_t)tb*BB*HH,
                       enc_whh_l1 + (size_t)GG*HH };
        lstm_step2<<<stepGrd, 256>>>(df, db);
    }

    // 4) heads
    head_kernel<<<BB, 256>>>(y1f + (size_t)(TT-1)*BB*HH, y1b,
                             fc_mu_w, fc_mu_b, fc_lv_w, fc_lv_b,
                             out_mu, out_lv, zbuf);

    // 5) decoder init + initial partial0
    dec_init_kernel<<<BB, 512>>>(zbuf, dec_in_w, dec_in_b, dh0, dh1, dc0, dc1, tokp);
    sgemm_bias_f<<<dim3(GG/PBN, BB/PBM), 256>>>(dh0, dec_whh, dec_b, part0, BB, GG, HH);

    // 6) autoregressive decode with partial pipelining
    dim3 decGrd(HH/RBN, BB/RBM, 2);    // (16, 8, 2) = 256 blocks
    for (int t = 0; t < TT; t++) {
        CellArgs c0 = { nullptr, tokp, dec_wih, part0, dc0, dh0 };
        PartArgs p1 = { dh1, dec_whh + (size_t)GG*HH, dec_b + GG, part1 };
        dec_step<<<decGrd, 256>>>(c0, p1, emb);
        CellArgs c1 = { dh0, nullptr, dec_wih + (size_t)GG*HH, part1, dc1, dh1 };
        PartArgs p0 = { dh0, dec_whh, dec_b, part0 };
        dec_step<<<decGrd, 256>>>(c1, p0, emb);
        logits_argmax_kernel<<<BB/4, 128>>>(dh1, dec_out_w, dec_out_b, out_recon, t, tokp);
    }
}

// round 5
// speedup vs baseline: 1.3479x; 1.3479x over previous
#include <cuda_runtime.h>
#include <math.h>

// ---------------- problem constants ----------------
#define TT 128   // seq len
#define BB 256   // batch
#define HH 512   // hidden
#define GG 2048  // 4*H gates
#define VV 128   // vocab
#define LL 128   // latent

typedef unsigned long long u64t;

// f32x2 packed helpers (sm_100+ PTX; FFMA2 in SASS — 2x fp32 throughput)
__device__ __forceinline__ u64t pack2(float x, float y) {
    u64t r; asm("mov.b64 %0, {%1, %2};" : "=l"(r) : "f"(x), "f"(y)); return r;
}
__device__ __forceinline__ void fma2(u64t& d, u64t a, u64t b) {
    asm("fma.rn.f32x2 %0, %1, %2, %0;" : "+l"(d) : "l"(a), "l"(b));
}
__device__ __forceinline__ void add2(u64t& d, u64t a) {
    asm("add.rn.f32x2 %0, %0, %1;" : "+l"(d) : "l"(a));
}
__device__ __forceinline__ float2 unpack2(u64t v) {
    float2 r; asm("mov.b64 {%0, %1}, %2;" : "=f"(r.x), "=f"(r.y) : "l"(v)); return r;
}

// ---------------- device scratch ----------------
__device__ float g_seq [TT*BB*HH];
__device__ float g_seq1[TT*BB*2*HH];
__device__ float g_preF[TT*BB*GG];
__device__ float g_preB[TT*BB*GG];
__device__ float g_y0f [TT*BB*HH];
__device__ float g_y0b [TT*BB*HH];
__device__ float g_y1f [TT*BB*HH];
__device__ float g_y1b [TT*BB*HH];
__device__ float g_c0f [BB*HH];
__device__ float g_c0b [BB*HH];
__device__ float g_c1f [BB*HH];
__device__ float g_c1b [BB*HH];
__device__ float g_zeros[BB*HH];     // never written -> stays zero
__device__ float g_z   [BB*LL];
__device__ float g_dh0 [BB*HH];
__device__ float g_dh1 [BB*HH];
__device__ float g_dc0 [BB*HH];
__device__ float g_dc1 [BB*HH];
__device__ float g_part0[BB*GG];
__device__ float g_part1[BB*GG];
__device__ int   g_tok [BB];

__device__ __forceinline__ float sigf(float v) { return 1.0f / (1.0f + expf(-v)); }

// ---------------- embedding gather ----------------
__global__ void embed_kernel(const int* __restrict__ x, const float* __restrict__ emb,
                             float* __restrict__ seq) {
    int total = TT*BB*HH;
    for (int i = blockIdx.x*blockDim.x + threadIdx.x; i < total; i += gridDim.x*blockDim.x) {
        int t = i / (BB*HH);
        int r = i % (BB*HH);
        int b = r / HH;
        int h = r % HH;
        seq[i] = emb[x[b*TT + t]*HH + h];
    }
}

// ---------------- concat ----------------
__global__ void concat_kernel(const float* __restrict__ yf, const float* __restrict__ yb,
                              float* __restrict__ seq1) {
    int total = TT*BB*2*HH;
    for (int i = blockIdx.x*blockDim.x + threadIdx.x; i < total; i += gridDim.x*blockDim.x) {
        int r = i / (2*HH);
        int j = i % (2*HH);
        seq1[i] = (j < HH) ? yf[r*HH + j] : yb[r*HH + j - HH];
    }
}

// ================= SGEMM (f32x2): C[M,N] = A[M,K] @ W[N,K]^T + bias[N] =================
#define PBM 128
#define PBN 128
#define PBK 16
#define PA_LD 132
#define PW_LD 132

__global__ __launch_bounds__(256) void sgemm_bias_f(const float* __restrict__ A,
                                                    const float* __restrict__ W,
                                                    const float* __restrict__ bias,
                                                    float* __restrict__ C,
                                                    int M, int N, int K) {
    __shared__ __align__(16) float As[PBK*PA_LD];
    __shared__ __align__(16) float Ws[PBK*PW_LD];
    const int bm = blockIdx.y * PBM;
    const int bn = blockIdx.x * PBN;
    const int tid = threadIdx.x;
    const int tx = tid % 16;
    const int ty = tid / 16;
    const int am = tid >> 1;
    const int ak = (tid & 1) * 8;

    const float* ap = A + (size_t)(bm + am)*K + ak;
    const float* wp = W + (size_t)(bn + am)*K + ak;

    float4 ra0 = *(const float4*)(ap);
    float4 ra1 = *(const float4*)(ap + 4);
    float4 rw0 = *(const float4*)(wp);
    float4 rw1 = *(const float4*)(wp + 4);

    u64t acc2[4][8];
    #pragma unroll
    for (int p = 0; p < 4; p++)
        #pragma unroll
        for (int j = 0; j < 8; j++) acc2[p][j] = 0ull;

    for (int k0 = 0; k0 < K; k0 += PBK) {
        As[(ak+0)*PA_LD + am] = ra0.x; As[(ak+1)*PA_LD + am] = ra0.y;
        As[(ak+2)*PA_LD + am] = ra0.z; As[(ak+3)*PA_LD + am] = ra0.w;
        As[(ak+4)*PA_LD + am] = ra1.x; As[(ak+5)*PA_LD + am] = ra1.y;
        As[(ak+6)*PA_LD + am] = ra1.z; As[(ak+7)*PA_LD + am] = ra1.w;
        Ws[(ak+0)*PW_LD + am] = rw0.x; Ws[(ak+1)*PW_LD + am] = rw0.y;
        Ws[(ak+2)*PW_LD + am] = rw0.z; Ws[(ak+3)*PW_LD + am] = rw0.w;
        Ws[(ak+4)*PW_LD + am] = rw1.x; Ws[(ak+5)*PW_LD + am] = rw1.y;
        Ws[(ak+6)*PW_LD + am] = rw1.z; Ws[(ak+7)*PW_LD + am] = rw1.w;
        __syncthreads();

        if (k0 + PBK < K) {
            ra0 = *(const float4*)(ap + k0 + PBK);
            ra1 = *(const float4*)(ap + k0 + PBK + 4);
            rw0 = *(const float4*)(wp + k0 + PBK);
            rw1 = *(const float4*)(wp + k0 + PBK + 4);
        }

        #pragma unroll
        for (int k = 0; k < PBK; k++) {
            ulonglong2 A0 = *(const ulonglong2*)&As[k*PA_LD + ty*8];
            ulonglong2 A1 = *(const ulonglong2*)&As[k*PA_LD + ty*8 + 4];
            u64t apair[4] = {A0.x, A0.y, A1.x, A1.y};
            float w[8];
            *(float4*)&w[0] = *(const float4*)&Ws[k*PW_LD + tx*8];
            *(float4*)&w[4] = *(const float4*)&Ws[k*PW_LD + tx*8 + 4];
            #pragma unroll
            for (int j = 0; j < 8; j++) {
                u64t w2 = pack2(w[j], w[j]);
                #pragma unroll
                for (int p = 0; p < 4; p++) fma2(acc2[p][j], apair[p], w2);
            }
        }
        __syncthreads();
    }

    float bb[8];
    *(float4*)&bb[0] = *(const float4*)(bias + bn + tx*8);
    *(float4*)&bb[4] = *(const float4*)(bias + bn + tx*8 + 4);
    #pragma unroll
    for (int p = 0; p < 4; p++) {
        float2 v[8];
        #pragma unroll
        for (int j = 0; j < 8; j++) v[j] = unpack2(acc2[p][j]);
        #pragma unroll
        for (int sub = 0; sub < 2; sub++) {
            size_t row = (size_t)(bm + ty*8 + 2*p + sub)*N + bn + tx*8;
            float o[8];
            #pragma unroll
            for (int j = 0; j < 8; j++) o[j] = (sub ? v[j].y : v[j].x) + bb[j];
            *(float4*)&C[row]     = *(float4*)&o[0];
            *(float4*)&C[row + 4] = *(float4*)&o[4];
        }
    }
}

// ====== 4-gate GEMM core, split-K, 512 threads: 64 batch x 32 hcols x 4 gates =========
// Warps 0-7 accumulate k in [0,256), warps 8-15 k in [256,512), each half with its own
// smem staging buffers. Same per-k LDS traffic and FFMA2 count as the round-3 core,
// but 2x warps per scheduler. Partials merged via smem with add.rn.f32x2.
#define RBM 64
#define RBN 32
#define RBK 32
#define KSPLIT 256           // k range per half
#define HS_LD 68             // (RBM+4)
#define WS_LD 33             // (RBN+1)
#define HS_FLOATS (RBK*HS_LD)            // 2176
#define WS_FLOATS (4*RBK*WS_LD)          // 4224
#define SMEM_FLOATS (2*HS_FLOATS + 2*WS_FLOATS)  // 12800 floats = 50 KB

template<bool GATHER>
__device__ __forceinline__ void gate_gemm_ks(const float* __restrict__ Abase,
                                             const int* __restrict__ tok,
                                             const float* __restrict__ emb,
                                             const float* __restrict__ W,
                                             int bm, int bn, int kbeg,
                                             float* __restrict__ Hs,
                                             float* __restrict__ Ws,
                                             u64t acc2[4][4]) {
    const int lt = threadIdx.x & 255;
    const int tx = lt & 31;        // col
    const int ty = lt >> 5;        // row-octet (0..7) -> rows ty*8..ty*8+7
    const int hm = lt >> 2;        // 0..63
    const int hk = (lt & 3) * 8;   // 0,8,16,24
    const int wr = lt >> 1;        // 0..127 = gate*32 + col
    const int wk = (lt & 1) * 16;  // 0 or 16
    const int wg = wr >> 5;
    const int wn = wr & 31;

    const float* hp;
    if (GATHER) hp = emb + (size_t)tok[bm + hm]*HH + kbeg + hk;
    else        hp = Abase + (size_t)(bm + hm)*HH + kbeg + hk;
    const float* wp = W + (size_t)(wg*HH + bn + wn)*HH + kbeg + wk;

    float4 ha0 = *(const float4*)(hp);
    float4 ha1 = *(const float4*)(hp + 4);
    float4 wa0 = *(const float4*)(wp);
    float4 wa1 = *(const float4*)(wp + 4);
    float4 wa2 = *(const float4*)(wp + 8);
    float4 wa3 = *(const float4*)(wp + 12);

    for (int kt = 0; kt < KSPLIT; kt += RBK) {
        Hs[(hk+0)*HS_LD + hm] = ha0.x; Hs[(hk+1)*HS_LD + hm] = ha0.y;
        Hs[(hk+2)*HS_LD + hm] = ha0.z; Hs[(hk+3)*HS_LD + hm] = ha0.w;
        Hs[(hk+4)*HS_LD + hm] = ha1.x; Hs[(hk+5)*HS_LD + hm] = ha1.y;
        Hs[(hk+6)*HS_LD + hm] = ha1.z; Hs[(hk+7)*HS_LD + hm] = ha1.w;
        Ws[(wg*RBK + wk+ 0)*WS_LD + wn] = wa0.x; Ws[(wg*RBK + wk+ 1)*WS_LD + wn] = wa0.y;
        Ws[(wg*RBK + wk+ 2)*WS_LD + wn] = wa0.z; Ws[(wg*RBK + wk+ 3)*WS_LD + wn] = wa0.w;
        Ws[(wg*RBK + wk+ 4)*WS_LD + wn] = wa1.x; Ws[(wg*RBK + wk+ 5)*WS_LD + wn] = wa1.y;
        Ws[(wg*RBK + wk+ 6)*WS_LD + wn] = wa1.z; Ws[(wg*RBK + wk+ 7)*WS_LD + wn] = wa1.w;
        Ws[(wg*RBK + wk+ 8)*WS_LD + wn] = wa2.x; Ws[(wg*RBK + wk+ 9)*WS_LD + wn] = wa2.y;
        Ws[(wg*RBK + wk+10)*WS_LD + wn] = wa2.z; Ws[(wg*RBK + wk+11)*WS_LD + wn] = wa2.w;
        Ws[(wg*RBK + wk+12)*WS_LD + wn] = wa3.x; Ws[(wg*RBK + wk+13)*WS_LD + wn] = wa3.y;
        Ws[(wg*RBK + wk+14)*WS_LD + wn] = wa3.z; Ws[(wg*RBK + wk+15)*WS_LD + wn] = wa3.w;
        __syncthreads();

        if (kt + RBK < KSPLIT) {
            ha0 = *(const float4*)(hp + kt + RBK);
            ha1 = *(const float4*)(hp + kt + RBK + 4);
            wa0 = *(const float4*)(wp + kt + RBK);
            wa1 = *(const float4*)(wp + kt + RBK + 4);
            wa2 = *(const float4*)(wp + kt + RBK + 8);
            wa3 = *(const float4*)(wp + kt + RBK + 12);
        }

        #pragma unroll 8
        for (int k = 0; k < RBK; k++) {
            ulonglong2 A0 = *(const ulonglong2*)&Hs[k*HS_LD + ty*8];
            ulonglong2 A1 = *(const ulonglong2*)&Hs[k*HS_LD + ty*8 + 4];
            u64t apair[4] = {A0.x, A0.y, A1.x, A1.y};
            #pragma unroll
            for (int g = 0; g < 4; g++) {
                float w = Ws[(g*RBK + k)*WS_LD + tx];
                u64t w2 = pack2(w, w);
                #pragma unroll
                for (int p = 0; p < 4; p++) fma2(acc2[g][p], apair[p], w2);
            }
        }
        __syncthreads();
    }
}

// Merge half-1 partials into half-0 accumulators via smem (reuses staging buffers).
__device__ __forceinline__ void ksplit_merge(float* __restrict__ smemAll,
                                             u64t acc2[4][4], int half) {
    u64t* red = reinterpret_cast<u64t*>(smemAll);   // 256*16 u64 = 32 KB < 50 KB
    const int lt = threadIdx.x & 255;
    if (half == 1) {
        #pragma unroll
        for (int g = 0; g < 4; g++)
            #pragma unroll
            for (int p = 0; p < 4; p++)
                red[lt*16 + g*4 + p] = acc2[g][p];
    }
    __syncthreads();
    if (half == 0) {
        #pragma unroll
        for (int g = 0; g < 4; g++)
            #pragma unroll
            for (int p = 0; p < 4; p++)
                add2(acc2[g][p], red[lt*16 + g*4 + p]);
    }
}

// LSTM elementwise epilogue (half-0 threads: 8 rows x 1 col each)
__device__ __forceinline__ void lstm_epilogue(u64t acc2[4][4],
                                              const float* __restrict__ pre,
                                              const float* __restrict__ cin,
                                              float* __restrict__ cout,
                                              float* __restrict__ hout,
                                              int bm, int bn) {
    const int lt = threadIdx.x & 255;
    const int tx = lt & 31;
    const int ty = lt >> 5;
    const int n = bn + tx;
    #pragma unroll
    for (int p = 0; p < 4; p++) {
        float2 vi = unpack2(acc2[0][p]);
        float2 vf = unpack2(acc2[1][p]);
        float2 vg = unpack2(acc2[2][p]);
        float2 vo = unpack2(acc2[3][p]);
        #pragma unroll
        for (int sub = 0; sub < 2; sub++) {
            int b = bm + ty*8 + 2*p + sub;
            const float* pb = pre + (size_t)b*GG;
            float gi = pb[0*HH + n] + (sub ? vi.y : vi.x);
            float gf = pb[1*HH + n] + (sub ? vf.y : vf.x);
            float gg = pb[2*HH + n] + (sub ? vg.y : vg.x);
            float go = pb[3*HH + n] + (sub ? vo.y : vo.x);
            float cn = sigf(gf)*cin[(size_t)b*HH + n] + sigf(gi)*tanhf(gg);
            cout[(size_t)b*HH + n] = cn;
            hout[(size_t)b*HH + n] = sigf(go)*tanhf(cn);
        }
    }
}

// ---------------- encoder recurrent step (both dirs via grid.z) ----------------
struct DirArgs {
    const float* pre;
    const float* hin;
    const float* cin;
    float* cout;
    float* hout;
    const float* Whh;
};

__global__ __launch_bounds__(512, 1) void lstm_step2(DirArgs A0, DirArgs A1) {
    __shared__ __align__(16) float S[SMEM_FLOATS];
    DirArgs d = blockIdx.z ? A1 : A0;
    const int half = threadIdx.x >> 8;
    float* Hs = S + half*HS_FLOATS;
    float* Ws = S + 2*HS_FLOATS + half*WS_FLOATS;
    int bm = blockIdx.y * RBM;
    int bn = blockIdx.x * RBN;
    u64t acc2[4][4];
    #pragma unroll
    for (int g = 0; g < 4; g++)
        #pragma unroll
        for (int p = 0; p < 4; p++) acc2[g][p] = 0ull;
    gate_gemm_ks<false>(d.hin, nullptr, nullptr, d.Whh, bm, bn, half*KSPLIT, Hs, Ws, acc2);
    ksplit_merge(S, acc2, half);
    if (half == 0)
        lstm_epilogue(acc2, d.pre, d.cin, d.cout, d.hout, bm, bn);
}

// ---------------- decoder fused step (cell via z=0, partial via z=1) ----------------
struct CellArgs {
    const float* A;
    const int*   tok;
    const float* W;
    const float* partial;
    float* c;
    float* h;
};
struct PartArgs {
    const float* A;
    const float* W;
    const float* bias;
    float* outp;
};

__global__ __launch_bounds__(512, 1) void dec_step(CellArgs ca, PartArgs pa,
                                                   const float* __restrict__ emb) {
    __shared__ __align__(16) float S[SMEM_FLOATS];
    const int half = threadIdx.x >> 8;
    float* Hs = S + half*HS_FLOATS;
    float* Ws = S + 2*HS_FLOATS + half*WS_FLOATS;
    int bm = blockIdx.y * RBM;
    int bn = blockIdx.x * RBN;
    u64t acc2[4][4];
    #pragma unroll
    for (int g = 0; g < 4; g++)
        #pragma unroll
        for (int p = 0; p < 4; p++) acc2[g][p] = 0ull;

    if (blockIdx.z == 0) {
        if (ca.tok) gate_gemm_ks<true >(nullptr, ca.tok, emb, ca.W, bm, bn, half*KSPLIT, Hs, Ws, acc2);
        else        gate_gemm_ks<false>(ca.A,   nullptr, nullptr, ca.W, bm, bn, half*KSPLIT, Hs, Ws, acc2);
        ksplit_merge(S, acc2, half);
        if (half == 0)
            lstm_epilogue(acc2, ca.partial, ca.c, ca.c, ca.h, bm, bn);
    } else {
        gate_gemm_ks<false>(pa.A, nullptr, nullptr, pa.W, bm, bn, half*KSPLIT, Hs, Ws, acc2);
        ksplit_merge(S, acc2, half);
        if (half == 0) {
            const int lt = threadIdx.x & 255;
            const int tx = lt & 31;
            const int ty = lt >> 5;
            const int n = bn + tx;
            #pragma unroll
            for (int g = 0; g < 4; g++) {
                float bv = pa.bias[g*HH + n];
                #pragma unroll
                for (int p = 0; p < 4; p++) {
                    float2 v = unpack2(acc2[g][p]);
                    int b0 = bm + ty*8 + 2*p;
                    pa.outp[(size_t)(b0+0)*GG + g*HH + n] = v.x + bv;
                    pa.outp[(size_t)(b0+1)*GG + g*HH + n] = v.y + bv;
                }
            }
        }
    }
}

// ---------------- mu/logvar heads ----------------
__global__ __launch_bounds__(256) void head_kernel(const float* __restrict__ hf,
                                                   const float* __restrict__ hb,
                                                   const float* __restrict__ Wmu,
                                                   const float* __restrict__ bmu,
                                                   const float* __restrict__ Wlv,
                                                   const float* __restrict__ blv,
                                                   float* __restrict__ out_mu,
                                                   float* __restrict__ out_lv,
                                                   float* __restrict__ zbuf) {
    int b = blockIdx.x;
    int tid = threadIdx.x;
    __shared__ float sh[2*HH];
    for (int i = tid; i < HH; i += 256) {
        sh[i]      = hf[b*HH + i];
        sh[HH + i] = hb[b*HH + i];
    }
    __syncthreads();
    const float* W;
    float acc;
    int l;
    if (tid < LL) { l = tid;      W = Wmu + (size_t)l*2*HH; acc = bmu[l]; }
    else          { l = tid - LL; W = Wlv + (size_t)l*2*HH; acc = blv[l]; }
    #pragma unroll 8
    for (int k = 0; k < 2*HH; k++) acc += sh[k]*W[k];
    if (tid < LL) { out_mu[b*LL + l] = acc; zbuf[b*LL + l] = acc; }
    else          { out_lv[b*LL + l] = acc; }
}

// ---------------- decoder init ----------------
__global__ __launch_bounds__(512) void dec_init_kernel(const float* __restrict__ z,
                                                       const float* __restrict__ W,
                                                       const float* __restrict__ bias,
                                                       float* __restrict__ h0,
                                                       float* __restrict__ h1,
                                                       float* __restrict__ c0,
                                                       float* __restrict__ c1,
                                                       int* __restrict__ tok) {
    int b = blockIdx.x;
    int tid = threadIdx.x;
    __shared__ float sz[LL];
    if (tid < LL) sz[tid] = z[b*LL + tid];
    __syncthreads();
    float acc = bias[tid];
    const float* w = W + (size_t)tid*LL;
    #pragma unroll 8
    for (int k = 0; k < LL; k++) acc += sz[k]*w[k];
    h0[b*HH + tid] = acc;
    h1[b*HH + tid] = acc;
    c0[b*HH + tid] = 0.0f;
    c1[b*HH + tid] = 0.0f;
    if (tid == 0) tok[b] = 1;
}

// ---------------- logits + argmax ----------------
__global__ __launch_bounds__(128) void logits_argmax_kernel(const float* __restrict__ h1,
                                                            const float* __restrict__ W,
                                                            const float* __restrict__ bias,
                                                            float* __restrict__ recon,
                                                            int t,
                                                            int* __restrict__ tok) {
    int v = threadIdx.x;
    int b0 = blockIdx.x * 4;
    __shared__ float sh[4][HH];
    for (int i = v; i < 4*HH/4; i += 128) {
        ((float4*)&sh[0][0])[i] = ((const float4*)(h1 + (size_t)b0*HH))[i];
    }
    __syncthreads();
    float bv = bias[v];
    float acc0 = bv, acc1 = bv, acc2 = bv, acc3 = bv;
    const float4* w4 = (const float4*)(W + (size_t)v*HH);
    #pragma unroll 4
    for (int k = 0; k < HH/4; k++) {
        float4 wv = w4[k];
        float4 s0 = *(const float4*)&sh[0][k*4];
        float4 s1 = *(const float4*)&sh[1][k*4];
        float4 s2 = *(const float4*)&sh[2][k*4];
        float4 s3 = *(const float4*)&sh[3][k*4];
        acc0 += s0.x*wv.x + s0.y*wv.y + s0.z*wv.z + s0.w*wv.w;
        acc1 += s1.x*wv.x + s1.y*wv.y + s1.z*wv.z + s1.w*wv.w;
        acc2 += s2.x*wv.x + s2.y*wv.y + s2.z*wv.z + s2.w*wv.w;
        acc3 += s3.x*wv.x + s3.y*wv.y + s3.z*wv.z + s3.w*wv.w;
    }
    __shared__ float sv[4][128];
    __shared__ int   si[4][128];
    float accs[4] = {acc0, acc1, acc2, acc3};
    #pragma unroll
    for (int i = 0; i < 4; i++) {
        recon[(size_t)(b0+i)*TT*VV + (size_t)t*VV + v] = accs[i];
        sv[i][v] = accs[i];
        si[i][v] = v;
    }
    __syncthreads();
    for (int s = 64; s > 0; s >>= 1) {
        if (v < s) {
            #pragma unroll
            for (int i = 0; i < 4; i++) {
                float ov = sv[i][v+s]; int oi = si[i][v+s];
                if (ov > sv[i][v] || (ov == sv[i][v] && oi < si[i][v])) {
                    sv[i][v] = ov; si[i][v] = oi;
                }
            }
        }
        __syncthreads();
    }
    if (v < 4) tok[b0 + v] = si[v][0];
}

// =================================== host launcher ====================================
extern "C" void kernel_launch(void* const* d_in, const int* in_sizes, int n_in,
                              void* d_out, int out_size) {
    const int*   x           = (const int*)  d_in[0];
    const float* emb         = (const float*)d_in[1];
    const float* enc_wih_l0  = (const float*)d_in[2];
    const float* enc_whh_l0  = (const float*)d_in[3];
    const float* enc_b_l0    = (const float*)d_in[4];
    const float* enc_wih_l1  = (const float*)d_in[5];
    const float* enc_whh_l1  = (const float*)d_in[6];
    const float* enc_b_l1    = (const float*)d_in[7];
    const float* fc_mu_w     = (const float*)d_in[8];
    const float* fc_mu_b     = (const float*)d_in[9];
    const float* fc_lv_w     = (const float*)d_in[10];
    const float* fc_lv_b     = (const float*)d_in[11];
    const float* dec_in_w    = (const float*)d_in[12];
    const float* dec_in_b    = (const float*)d_in[13];
    const float* dec_wih     = (const float*)d_in[14];
    const float* dec_whh     = (const float*)d_in[15];
    const float* dec_b       = (const float*)d_in[16];
    const float* dec_out_w   = (const float*)d_in[17];
    const float* dec_out_b   = (const float*)d_in[18];

    float* out       = (float*)d_out;
    float* out_recon = out;
    float* out_mu    = out + (size_t)BB*TT*VV;
    float* out_lv    = out_mu + (size_t)BB*LL;

    float *seq, *seq1, *preF, *preB, *y0f, *y0b, *y1f, *y1b;
    float *c0f, *c0b, *c1f, *c1b, *zeros, *zbuf, *dh0, *dh1, *dc0, *dc1;
    float *part0, *part1;
    int* tokp;
    cudaGetSymbolAddress((void**)&seq,   g_seq);
    cudaGetSymbolAddress((void**)&seq1,  g_seq1);
    cudaGetSymbolAddress((void**)&preF,  g_preF);
    cudaGetSymbolAddress((void**)&preB,  g_preB);
    cudaGetSymbolAddress((void**)&y0f,   g_y0f);
    cudaGetSymbolAddress((void**)&y0b,   g_y0b);
    cudaGetSymbolAddress((void**)&y1f,   g_y1f);
    cudaGetSymbolAddress((void**)&y1b,   g_y1b);
    cudaGetSymbolAddress((void**)&c0f,   g_c0f);
    cudaGetSymbolAddress((void**)&c0b,   g_c0b);
    cudaGetSymbolAddress((void**)&c1f,   g_c1f);
    cudaGetSymbolAddress((void**)&c1b,   g_c1b);
    cudaGetSymbolAddress((void**)&zeros, g_zeros);
    cudaGetSymbolAddress((void**)&zbuf,  g_z);
    cudaGetSymbolAddress((void**)&dh0,   g_dh0);
    cudaGetSymbolAddress((void**)&dh1,   g_dh1);
    cudaGetSymbolAddress((void**)&dc0,   g_dc0);
    cudaGetSymbolAddress((void**)&dc1,   g_dc1);
    cudaGetSymbolAddress((void**)&part0, g_part0);
    cudaGetSymbolAddress((void**)&part1, g_part1);
    cudaGetSymbolAddress((void**)&tokp,  g_tok);

    // 1) embedding
    embed_kernel<<<2048, 256>>>(x, emb, seq);

    // 2) encoder layer 0 pre-GEMMs
    dim3 preGrd(GG/PBN, (TT*BB)/PBM);
    sgemm_bias_f<<<preGrd, 256>>>(seq, enc_wih_l0,                 enc_b_l0,      preF, TT*BB, GG, HH);
    sgemm_bias_f<<<preGrd, 256>>>(seq, enc_wih_l0 + (size_t)GG*HH, enc_b_l0 + GG, preB, TT*BB, GG, HH);

    dim3 stepGrd(HH/RBN, BB/RBM, 2);   // (16, 4, 2) = 128 blocks x 512 threads
    for (int s = 0; s < TT; s++) {
        int tf = s, tb = TT-1-s;
        DirArgs df = { preF + (size_t)tf*BB*GG,
                       (s ? y0f + (size_t)(tf-1)*BB*HH : zeros),
                       (s ? c0f : zeros), c0f,
                       y0f + (size_t)tf*BB*HH,
                       enc_whh_l0 };
        DirArgs db = { preB + (size_t)tb*BB*GG,
                       (s ? y0b + (size_t)(tb+1)*BB*HH : zeros),
                       (s ? c0b : zeros), c0b,
                       y0b + (size_t)tb*BB*HH,
                       enc_whh_l0 + (size_t)GG*HH };
        lstm_step2<<<stepGrd, 512>>>(df, db);
    }

    // 3) encoder layer 1
    concat_kernel<<<2048, 256>>>(y0f, y0b, seq1);
    sgemm_bias_f<<<preGrd, 256>>>(seq1, enc_wih_l1,                   enc_b_l1,      preF, TT*BB, GG, 2*HH);
    sgemm_bias_f<<<preGrd, 256>>>(seq1, enc_wih_l1 + (size_t)GG*2*HH, enc_b_l1 + GG, preB, TT*BB, GG, 2*HH);
    for (int s = 0; s < TT; s++) {
        int tf = s, tb = TT-1-s;
        DirArgs df = { preF + (size_t)tf*BB*GG,
                       (s ? y1f + (size_t)(tf-1)*BB*HH : zeros),
                       (s ? c1f : zeros), c1f,
                       y1f + (size_t)tf*BB*HH,
                       enc_whh_l1 };
        DirArgs db = { preB + (size_t)tb*BB*GG,
                       (s ? y1b + (size_t)(tb+1)*BB*HH : zeros),
                       (s ? c1b : zeros), c1b,
                       y1b + (size_t)tb*BB*HH,
                       enc_whh_l1 + (size_t)GG*HH };
        lstm_step2<<<stepGrd, 512>>>(df, db);
    }

    // 4) heads
    head_kernel<<<BB, 256>>>(y1f + (size_t)(TT-1)*BB*HH, y1b,
                             fc_mu_w, fc_mu_b, fc_lv_w, fc_lv_b,
                             out_mu, out_lv, zbuf);

    // 5) decoder init + initial partial0
    dec_init_kernel<<<BB, 512>>>(zbuf, dec_in_w, dec_in_b, dh0, dh1, dc0, dc1, tokp);
    sgemm_bias_f<<<dim3(GG/PBN, BB/PBM), 256>>>(dh0, dec_whh, dec_b, part0, BB, GG, HH);

    // 6) autoregressive decode with partial pipelining
    dim3 decGrd(HH/RBN, BB/RBM, 2);    // (16, 4, 2) = 128 blocks x 512 threads
    for (int t = 0; t < TT; t++) {
        CellArgs c0 = { nullptr, tokp, dec_wih, part0, dc0, dh0 };
        PartArgs p1 = { dh1, dec_whh + (size_t)GG*HH, dec_b + GG, part1 };
        dec_step<<<decGrd, 512>>>(c0, p1, emb);
        CellArgs c1 = { dh0, nullptr, dec_wih + (size_t)GG*HH, part1, dc1, dh1 };
        PartArgs p0 = { dh0, dec_whh, dec_b, part0 };
        dec_step<<<decGrd, 512>>>(c1, p0, emb);
        logits_argmax_kernel<<<BB/4, 128>>>(dh1, dec_out_w, dec_out_b, out_recon, t, tokp);
    }
}